// round 14
// baseline (speedup 1.0000x reference)
#include <cuda_runtime.h>
#include <math.h>
#include <stdint.h>

#define B_   16384
#define KDIM 3072

// ---------------- gate descriptor table ----------------
// type: 0=U3(wire a), 1=ZZ(a,b), 2=YY, 3=XX, 4=CU3(ctrl=a,tgt=b), 5=ARB(pauli w0 on a, w1 on b)
typedef struct { int type, a, b, src, off, w0, w1; } GateDesc;

__constant__ GateDesc g_desc[66] = {
  {0,0,0,0,0,0,0},{0,2,0,0,33,0,0},{1,0,2,0,6,0,0},{2,0,2,0,7,0,0},{3,0,2,0,8,0,0},{0,0,0,0,9,0,0},{0,2,0,0,42,0,0},
  {0,1,0,0,15,0,0},{0,3,0,0,48,0,0},{1,1,3,0,21,0,0},{2,1,3,0,22,0,0},{3,1,3,0,23,0,0},{0,1,0,0,24,0,0},{0,3,0,0,57,0,0},
  {0,4,0,0,60,0,0},{0,6,0,0,93,0,0},{1,4,6,0,66,0,0},{2,4,6,0,67,0,0},{3,4,6,0,68,0,0},{0,4,0,0,69,0,0},{0,6,0,0,102,0,0},
  {0,5,0,0,75,0,0},{0,7,0,0,108,0,0},{1,5,7,0,81,0,0},{2,5,7,0,82,0,0},{3,5,7,0,83,0,0},{0,5,0,0,84,0,0},{0,7,0,0,117,0,0},
  {4,1,0,1,0,0,0},{4,3,2,1,3,0,0},{4,5,4,1,6,0,0},{4,7,6,1,9,0,0},
  {0,0,0,0,120,0,0},{0,2,0,0,153,0,0},{1,0,2,0,126,0,0},{2,0,2,0,127,0,0},{3,0,2,0,128,0,0},{0,0,0,0,129,0,0},{0,2,0,0,162,0,0},
  {0,4,0,0,180,0,0},{0,4,0,0,183,0,0},{0,4,0,0,186,0,0},{0,4,0,0,189,0,0},{0,4,0,0,192,0,0},
  {0,6,0,0,210,0,0},{0,6,0,0,213,0,0},{0,6,0,0,216,0,0},{0,6,0,0,219,0,0},{0,6,0,0,222,0,0},
  {4,2,0,1,12,0,0},{4,6,4,1,15,0,0},
  {5,0,4,2,0,1,0},{5,0,4,2,1,2,0},{5,0,4,2,2,3,0},{5,0,4,2,3,3,1},{5,0,4,2,4,0,1},
  {5,0,4,2,5,1,1},{5,0,4,2,6,2,1},{5,0,4,2,7,2,2},{5,0,4,2,8,3,2},{5,0,4,2,9,0,2},
  {5,0,4,2,10,1,2},{5,0,4,2,11,1,3},{5,0,4,2,12,2,3},{5,0,4,2,13,3,3},{5,0,4,2,14,0,3}
};

__constant__ float2 PT[4][4] = {
  {{1.f,0.f},{0.f,0.f},{0.f,0.f},{1.f,0.f}},
  {{0.f,0.f},{1.f,0.f},{1.f,0.f},{0.f,0.f}},
  {{0.f,0.f},{0.f,-1.f},{0.f,1.f},{0.f,0.f}},
  {{1.f,0.f},{0.f,0.f},{0.f,0.f},{-1.f,0.f}}
};

// ---------------- device scratch ----------------
__device__ float2 d_U[256*256];    // U[k*256 + col]
__device__ float  d_M[256*256];    // A = Re(U^dag Z0 U)
__device__ float4 d_mpad[2187];    // 6561 Pauli coeffs, groups of 3 padded to float4
__device__ float2 d_trig[B_*8];    // (sin,cos) of tanh(x@W^T+b)
__device__ float  d_part[9*B_];    // partial contractions per slice

__device__ __forceinline__ float2 cm(float2 a, float2 b){
    return make_float2(a.x*b.x - a.y*b.y, a.x*b.y + a.y*b.x);
}
__device__ __forceinline__ float2 ca(float2 a, float2 b){
    return make_float2(a.x+b.x, a.y+b.y);
}
__device__ __forceinline__ void ffma2(unsigned long long &acc, unsigned long long a, unsigned long long b){
    asm("fma.rn.f32x2 %0, %1, %2, %0;" : "+l"(acc) : "l"(a), "l"(b));
}
__device__ __forceinline__ uint32_t smem_u32(const void* p){
    uint32_t a;
    asm("{ .reg .u64 t; cvta.to.shared.u64 t, %1; cvt.u32.u64 %0, t; }" : "=r"(a) : "l"(p));
    return a;
}
// bulk async copy global->shared completing on mbarrier (UBLKCP; no tensor map)
__device__ __forceinline__ void bulk_g2s(uint32_t dst, const void* src, uint32_t bytes, uint32_t mbar){
    asm volatile("cp.async.bulk.shared::cta.global.mbarrier::complete_tx::bytes [%0], [%1], %2, [%3];"
                 :: "r"(dst), "l"(src), "r"(bytes), "r"(mbar) : "memory");
}
__device__ __forceinline__ void mbar_init(uint32_t mbar, uint32_t cnt){
    asm volatile("mbarrier.init.shared.b64 [%0], %1;" :: "r"(mbar), "r"(cnt) : "memory");
}
__device__ __forceinline__ void mbar_expect(uint32_t mbar, uint32_t bytes){
    asm volatile("mbarrier.arrive.expect_tx.shared.b64 _, [%0], %1;" :: "r"(mbar), "r"(bytes) : "memory");
}
__device__ __forceinline__ void mbar_wait(uint32_t mbar, uint32_t phase){
    asm volatile(
        "{\n\t.reg .pred P;\n\t"
        "WAIT_%=:\n\t"
        "mbarrier.try_wait.parity.acquire.cta.shared::cta.b64 P, [%0], %1, 0x989680;\n\t"
        "@P bra.uni DONE_%=;\n\t"
        "bra.uni WAIT_%=;\n\t"
        "DONE_%=:\n\t}"
        :: "r"(mbar), "r"(phase) : "memory");
}

// ---------------- gate construction (device fn) ----------------
__device__ void make_gate(int g, const float* conv, const float* pool,
                          const float* last, float2* out) {
    GateDesc d = g_desc[g];
    const float* src = (d.src==0) ? conv : ((d.src==1) ? pool : last);
    float2 M[16];
    #pragma unroll
    for (int i=0;i<16;i++) M[i]=make_float2(0.f,0.f);

    if (d.type==0 || d.type==4) {
        float th=src[d.off], ph=src[d.off+1], lam=src[d.off+2];
        float s,c;   sincosf(0.5f*th,&s,&c);
        float sl,cl; sincosf(lam,&sl,&cl);
        float sp,cp; sincosf(ph,&sp,&cp);
        float spl,cpl; sincosf(ph+lam,&spl,&cpl);
        float2 u00=make_float2(c,0.f),       u01=make_float2(-cl*s,-sl*s);
        float2 u10=make_float2(cp*s,sp*s),   u11=make_float2(cpl*c,spl*c);
        if (d.type==0) { M[0]=u00; M[1]=u01; M[2]=u10; M[3]=u11; }
        else {
            M[0]=make_float2(1.f,0.f); M[5]=make_float2(1.f,0.f);
            M[10]=u00; M[11]=u01; M[14]=u10; M[15]=u11;
        }
    } else if (d.type<=3) {
        float phi=src[d.off]; float s,c; sincosf(0.5f*phi,&s,&c);
        if (d.type==1) {
            M[0]=make_float2(c,-s); M[5]=make_float2(c,s);
            M[10]=make_float2(c,s); M[15]=make_float2(c,-s);
        } else {
            M[0]=M[5]=M[10]=M[15]=make_float2(c,0.f);
            if (d.type==3) {
                M[3]=M[6]=M[9]=M[12]=make_float2(0.f,-s);
            } else {
                M[3]=make_float2(0.f,s);  M[6]=make_float2(0.f,-s);
                M[9]=make_float2(0.f,-s); M[12]=make_float2(0.f,s);
            }
        }
    } else {
        float th=src[d.off]; float s,c; sincosf(0.5f*th,&s,&c);
        #pragma unroll
        for (int i=0;i<4;i++)
          #pragma unroll
          for (int j=0;j<4;j++){
            float2 pa = PT[d.w0][(i>>1)*2+(j>>1)];
            float2 pb = PT[d.w1][(i&1)*2+(j&1)];
            float2 K  = cm(pa,pb);
            float2 v  = make_float2(s*K.y, -s*K.x);
            if (i==j) v.x += c;
            M[i*4+j]=v;
        }
    }
    #pragma unroll
    for (int i=0;i<16;i++) out[i]=M[i];
}

// ---------------- 1. build gates (in smem) + evolve 256 basis cols -> U ----------------
__global__ void __launch_bounds__(256) k_build(const float* __restrict__ conv,
                                               const float* __restrict__ pool,
                                               const float* __restrict__ last) {
    __shared__ float2 sG[66*16];
    __shared__ float2 sp[4][256];
    int tid=threadIdx.x, sub=tid>>6, t=tid&63;
    if (tid < 66) make_gate(tid, conv, pool, last, &sG[tid*16]);
    int col = blockIdx.x*4 + sub;
    float2* p = sp[sub];
    for (int k=t;k<256;k+=64) p[k]=make_float2(k==col?1.f:0.f, 0.f);
    __syncthreads();

    for (int g=0; g<66; g++) {
        GateDesc d = g_desc[g];
        const float2* G = sG + g*16;
        if (d.type==0) {
            float2 g0=G[0],g1=G[1],g2=G[2],g3=G[3];
            int pos=7-d.a, mask=1<<pos;
            #pragma unroll
            for (int q=t;q<128;q+=64) {
                int k0 = ((q>>pos)<<(pos+1)) | (q & (mask-1));
                float2 a0=p[k0], a1=p[k0|mask];
                p[k0]      = ca(cm(g0,a0), cm(g1,a1));
                p[k0|mask] = ca(cm(g2,a0), cm(g3,a1));
            }
        } else {
            int pa=7-d.a, pb=7-d.b;
            int p1 = pa<pb?pa:pb, p2 = pa<pb?pb:pa;
            int ma=1<<pa, mb=1<<pb;
            int low = t & ((1<<p1)-1);
            int mid = ((t >> p1) & ((1<<(p2-1-p1))-1)) << (p1+1);
            int hi  = (t >> (p2-1)) << (p2+1);
            int k0 = hi|mid|low;
            float2 v0=p[k0], v1=p[k0|mb], v2=p[k0|ma], v3=p[k0|ma|mb];
            float2 r0 = ca(ca(cm(G[0],v0), cm(G[1],v1)), ca(cm(G[2],v2), cm(G[3],v3)));
            float2 r1 = ca(ca(cm(G[4],v0), cm(G[5],v1)), ca(cm(G[6],v2), cm(G[7],v3)));
            float2 r2 = ca(ca(cm(G[8],v0), cm(G[9],v1)), ca(cm(G[10],v2),cm(G[11],v3)));
            float2 r3 = ca(ca(cm(G[12],v0),cm(G[13],v1)), ca(cm(G[14],v2),cm(G[15],v3)));
            p[k0]=r0; p[k0|mb]=r1; p[k0|ma]=r2; p[k0|ma|mb]=r3;
        }
        __syncthreads();
    }
    for (int k=t;k<256;k+=64) d_U[k*256+col]=p[k];
}

// ---------------- 2. A = Re(U^dag S U), S = Z on bit7 (R8 proven) ----------------
// 256 blocks (row i) x 1024 threads (j, k-quarter); smem reduce
__global__ void __launch_bounds__(1024) k_M() {
    __shared__ float2 su[256];
    __shared__ float  sred[1024];
    int i = blockIdx.x;
    int t = threadIdx.x;
    int j = t & 255, ks = t >> 8;
    if (t < 256) {
        float2 u = d_U[t*256 + i];
        float sgn = (t & 128) ? -1.f : 1.f;
        su[t] = make_float2(u.x*sgn, u.y*sgn);
    }
    __syncthreads();
    unsigned long long acc = 0ull;
    const unsigned long long* ub = (const unsigned long long*)d_U;
    int k0 = ks*64;
    #pragma unroll 8
    for (int k=k0; k<k0+64; k++){
        unsigned long long a = *(const unsigned long long*)&su[k];
        ffma2(acc, a, ub[k*256 + j]);
    }
    float2 v2 = *(float2*)&acc;
    sred[t] = v2.x + v2.y;
    __syncthreads();
    if (ks == 0)
        d_M[i*256 + j] = sred[j] + sred[256+j] + sred[512+j] + sred[768+j];
}

// ---------------- 3. Pauli coefficients via Walsh-Hadamard ----------------
// block = xm (256 blocks), thread = i; H[z] = sum_i (-1)^{popc(i&z)} M[i, i^x]
__global__ void __launch_bounds__(256) k_coeff() {
    __shared__ float sv[256];
    int x = blockIdx.x, tid = threadIdx.x;
    float v = d_M[tid*256 + (tid ^ x)];
    #pragma unroll
    for (int s=0;s<5;s++){
        float p = __shfl_xor_sync(0xffffffffu, v, 1<<s);
        v = (tid & (1<<s)) ? (p - v) : (v + p);
    }
    sv[tid] = v;
    __syncthreads();
    #pragma unroll
    for (int s=5;s<8;s++){
        float p = sv[tid ^ (1<<s)];
        float nv = (tid & (1<<s)) ? (p - v) : (v + p);
        __syncthreads();
        sv[tid] = nv; v = nv;
        __syncthreads();
    }
    int z = tid;
    if ((z & x) == 0) {
        int word = 0, p3 = 1;
        #pragma unroll
        for (int w=0; w<8; w++){
            int dg = ((x>>w)&1) ? 1 : (((z>>w)&1) ? 2 : 0);
            word += dg * p3; p3 *= 3;
        }
        ((float*)d_mpad)[(word/3)*4 + word%3] = v * (1.f/256.f);
    }
}

// ---------------- 4. GEMM + tanh + sincos — bulk-async producer (UBLKCP) ----------------
// 256 CTAs x 512 threads, 1 CTA/SM. Warps = k-quads (broadcast W reads, proven),
// lanes = rows. Producer: warp 0 issues 64 cp.async.bulk (256B rows) per chunk
// into 272B-pitched smem rows (conflict-free LDS.128), completing on an
// mbarrier ring of 6 stages. W = ONE 96KB bulk copy. This removes the LDGSTS
// issue bottleneck (1024 ops/chunk -> 64) that pinned all prior variants at 48us.
#define XPITCH   272                       // bytes per row in a stage
#define XSTAGEB  (64*XPITCH)               // 17408 B per stage
#define NSTAGE   6
#define SMEM_W_B 98304
#define SMEM_X_B (NSTAGE*XSTAGEB)          // 104448
#define MBAR_OFF (SMEM_W_B + SMEM_X_B)     // 202752
#define GEMM_SMEM (MBAR_OFF + 64)          // 202816 B
__global__ void __launch_bounds__(512,1) k_gemm(const float* __restrict__ x,
                                                const float* __restrict__ w,
                                                const float* __restrict__ b) {
    extern __shared__ float sdyn[];
    float* sW = sdyn;                       // [8][3072] = 96KB, uniform reads
    int tid = threadIdx.x;
    int warp = tid>>5, lane = tid&31;
    int row0 = blockIdx.x*64;
    uint32_t base_u = smem_u32(sdyn);
    uint32_t sx_u   = base_u + SMEM_W_B;
    uint32_t mb_u   = base_u + MBAR_OFF;    // mb[0..5]=x stages, mb[6]=W

    if (tid == 0){
        #pragma unroll
        for (int s=0; s<NSTAGE+1; s++) mbar_init(mb_u + s*8, 1);
    }
    __syncthreads();
    asm volatile("fence.proxy.async.shared::cta;" ::: "memory");

    // producer warp: W (one bulk copy) + prime stages 0..5
    if (warp == 0){
        if (lane == 0){
            mbar_expect(mb_u + NSTAGE*8, SMEM_W_B);
            bulk_g2s(base_u, w, SMEM_W_B, mb_u + NSTAGE*8);
            #pragma unroll
            for (int s=0; s<NSTAGE; s++) mbar_expect(mb_u + s*8, 16384);
        }
        __syncwarp();
        #pragma unroll
        for (int s=0; s<NSTAGE; s++){
            #pragma unroll
            for (int u=0; u<2; u++){
                int r = lane + u*32;
                bulk_g2s(sx_u + s*XSTAGEB + r*XPITCH,
                         x + (size_t)(row0+r)*KDIM + s*64, 256, mb_u + s*8);
            }
        }
    }

    // wait for W once
    mbar_wait(mb_u + NSTAGE*8, 0);

    unsigned long long acc[2][8];
    #pragma unroll
    for (int r=0;r<2;r++)
      #pragma unroll
      for (int j=0;j<8;j++) acc[r][j]=0ull;

    for (int c=0; c<48; c++){
        int slot = c % NSTAGE;
        mbar_wait(mb_u + slot*8, (c/NSTAGE)&1);

        unsigned long long wlo[8], whi[8];
        #pragma unroll
        for (int j=0;j<8;j++){
            float4 wf = *(const float4*)&sW[j*KDIM + c*64 + warp*4];
            wlo[j] = *(unsigned long long*)&wf.x;
            whi[j] = *(unsigned long long*)&wf.z;
        }
        const char* xbase = (const char*)sdyn + SMEM_W_B + slot*XSTAGEB;
        #pragma unroll
        for (int r2=0;r2<2;r2++){
            int r = lane + r2*32;
            float4 xf = *(const float4*)(xbase + r*XPITCH + warp*16);
            unsigned long long xl = *(unsigned long long*)&xf.x;
            unsigned long long xh = *(unsigned long long*)&xf.z;
            #pragma unroll
            for (int j=0;j<8;j++){
                ffma2(acc[r2][j], xl, wlo[j]);
                ffma2(acc[r2][j], xh, whi[j]);
            }
        }

        __syncthreads();   // slot consumption complete CTA-wide
        if (warp == 0 && c+NSTAGE < 48){
            int ch = c + NSTAGE;           // refills the slot just freed
            if (lane == 0) mbar_expect(mb_u + slot*8, 16384);
            __syncwarp();
            #pragma unroll
            for (int u=0; u<2; u++){
                int r = lane + u*32;
                bulk_g2s(sx_u + slot*XSTAGEB + r*XPITCH,
                         x + (size_t)(row0+r)*KDIM + ch*64, 256, mb_u + slot*8);
            }
        }
    }

    // cross-warp k-reduction via smem (reuse x region: 32KB needed)
    __syncthreads();
    float* sred = sdyn + SMEM_W_B/4;
    #pragma unroll
    for (int r2=0;r2<2;r2++){
        int r = lane + r2*32;
        #pragma unroll
        for (int j=0;j<8;j++){
            float2 v = *(float2*)&acc[r2][j];
            sred[(warp*64 + r)*8 + j] = v.x + v.y;
        }
    }
    __syncthreads();
    {
        int r = tid>>3, j = tid&7;   // 512 threads = 64 rows x 8 outputs
        float a = 0.f;
        #pragma unroll
        for (int wp=0; wp<16; wp++) a += sred[(wp*64 + r)*8 + j];
        float th = tanhf(a + b[j]);
        float sn, cs; sincosf(th,&sn,&cs);
        d_trig[(row0+r)*8 + j] = make_float2(sn,cs);
    }
}

// ---------------- 5. contraction, 9 slices (p0,p1) — R8 proven ----------------
__global__ void __launch_bounds__(256) k_contract() {
    __shared__ float4 sm[243];
    int tid = threadIdx.x;
    int s01 = blockIdx.y;
    if (tid < 243) sm[tid] = d_mpad[s01*243 + tid];
    __syncthreads();

    int bidx = blockIdx.x*256 + tid;
    float2 tg[8];
    #pragma unroll
    for (int w=0;w<8;w++) tg[w] = d_trig[bidx*8 + w];

    float g2[3]={1.f,tg[2].x,tg[2].y}, g3[3]={1.f,tg[3].x,tg[3].y};
    float g4[3]={1.f,tg[4].x,tg[4].y}, g5[3]={1.f,tg[5].x,tg[5].y};
    float g6[3]={1.f,tg[6].x,tg[6].y};
    float s7=tg[7].x, c7=tg[7].y;

    float z=0.f; int idx=0;
    #pragma unroll 1
    for (int i2=0;i2<3;i2++){ float p2=g2[i2];
      #pragma unroll 1
      for (int i3=0;i3<3;i3++){ float p3=p2*g3[i3];
        #pragma unroll 1
        for (int i4=0;i4<3;i4++){ float p4=p3*g4[i4];
          #pragma unroll
          for (int i5=0;i5<3;i5++){ float p5=p4*g5[i5];
            #pragma unroll
            for (int i6=0;i6<3;i6++){ float p6=p5*g6[i6];
              float4 m = sm[idx++];
              z += p6*(m.x + m.y*s7 + m.z*c7);
            }
          }
        }
      }
    }
    int s0=s01/3, s1=s01%3;
    float f0 = (s0==0)?1.f:((s0==1)?tg[0].x:tg[0].y);
    float f1 = (s1==0)?1.f:((s1==1)?tg[1].x:tg[1].y);
    d_part[s01*B_ + bidx] = z * f0 * f1;
}

// ---------------- 6. logits ----------------
__global__ void __launch_bounds__(256) k_logits(const float* __restrict__ ow,
                                                const float* __restrict__ ob,
                                                float* __restrict__ out) {
    int bidx = blockIdx.x*256 + threadIdx.x;
    float z = 0.f;
    #pragma unroll
    for (int s=0;s<9;s++) z += d_part[s*B_ + bidx];
    #pragma unroll
    for (int c=0;c<10;c++) out[bidx*10 + c] = z*ow[c] + ob[c];
}

// ---------------- launch (R8 submission order, byte-identical) ----------------
extern "C" void kernel_launch(void* const* d_in, const int* in_sizes, int n_in,
                              void* d_out, int out_size) {
    const float* x    = (const float*)d_in[0];
    const float* fw   = (const float*)d_in[1];
    const float* fb   = (const float*)d_in[2];
    const float* conv = (const float*)d_in[3];
    const float* pool = (const float*)d_in[4];
    const float* last = (const float*)d_in[5];
    const float* ow   = (const float*)d_in[6];
    const float* ob   = (const float*)d_in[7];
    float* out = (float*)d_out;

    static int inited = 0;
    static cudaStream_t s2;
    static cudaEvent_t evFork, evJoin;
    if (!inited) {
        cudaFuncSetAttribute(k_gemm, cudaFuncAttributeMaxDynamicSharedMemorySize, GEMM_SMEM);
        cudaStreamCreateWithFlags(&s2, cudaStreamNonBlocking);
        cudaEventCreateWithFlags(&evFork, cudaEventDisableTiming);
        cudaEventCreateWithFlags(&evJoin, cudaEventDisableTiming);
        inited = 1;
    }

    // fork: circuit chain (build -> M -> coeff) on s2, gemm on main stream
    cudaEventRecord(evFork, 0);
    cudaStreamWaitEvent(s2, evFork, 0);

    k_build<<<64,256,0,s2>>>(conv, pool, last);
    k_M<<<256,1024,0,s2>>>();
    k_coeff<<<256,256,0,s2>>>();
    cudaEventRecord(evJoin, s2);

    k_gemm<<<256,512,GEMM_SMEM>>>(x, fw, fb);

    // join: contract needs both branches
    cudaStreamWaitEvent(0, evJoin, 0);
    dim3 gc(64,9);
    k_contract<<<gc,256>>>();
    k_logits<<<64,256>>>(ow, ob, out);
}

// round 15
// speedup vs baseline: 1.8587x; 1.8587x over previous
#include <cuda_runtime.h>
#include <math.h>
#include <stdint.h>

#define B_   16384
#define KDIM 3072

// ---------------- gate descriptor table ----------------
// type: 0=U3(wire a), 1=ZZ(a,b), 2=YY, 3=XX, 4=CU3(ctrl=a,tgt=b), 5=ARB(pauli w0 on a, w1 on b)
typedef struct { int type, a, b, src, off, w0, w1; } GateDesc;

__constant__ GateDesc g_desc[66] = {
  {0,0,0,0,0,0,0},{0,2,0,0,33,0,0},{1,0,2,0,6,0,0},{2,0,2,0,7,0,0},{3,0,2,0,8,0,0},{0,0,0,0,9,0,0},{0,2,0,0,42,0,0},
  {0,1,0,0,15,0,0},{0,3,0,0,48,0,0},{1,1,3,0,21,0,0},{2,1,3,0,22,0,0},{3,1,3,0,23,0,0},{0,1,0,0,24,0,0},{0,3,0,0,57,0,0},
  {0,4,0,0,60,0,0},{0,6,0,0,93,0,0},{1,4,6,0,66,0,0},{2,4,6,0,67,0,0},{3,4,6,0,68,0,0},{0,4,0,0,69,0,0},{0,6,0,0,102,0,0},
  {0,5,0,0,75,0,0},{0,7,0,0,108,0,0},{1,5,7,0,81,0,0},{2,5,7,0,82,0,0},{3,5,7,0,83,0,0},{0,5,0,0,84,0,0},{0,7,0,0,117,0,0},
  {4,1,0,1,0,0,0},{4,3,2,1,3,0,0},{4,5,4,1,6,0,0},{4,7,6,1,9,0,0},
  {0,0,0,0,120,0,0},{0,2,0,0,153,0,0},{1,0,2,0,126,0,0},{2,0,2,0,127,0,0},{3,0,2,0,128,0,0},{0,0,0,0,129,0,0},{0,2,0,0,162,0,0},
  {0,4,0,0,180,0,0},{0,4,0,0,183,0,0},{0,4,0,0,186,0,0},{0,4,0,0,189,0,0},{0,4,0,0,192,0,0},
  {0,6,0,0,210,0,0},{0,6,0,0,213,0,0},{0,6,0,0,216,0,0},{0,6,0,0,219,0,0},{0,6,0,0,222,0,0},
  {4,2,0,1,12,0,0},{4,6,4,1,15,0,0},
  {5,0,4,2,0,1,0},{5,0,4,2,1,2,0},{5,0,4,2,2,3,0},{5,0,4,2,3,3,1},{5,0,4,2,4,0,1},
  {5,0,4,2,5,1,1},{5,0,4,2,6,2,1},{5,0,4,2,7,2,2},{5,0,4,2,8,3,2},{5,0,4,2,9,0,2},
  {5,0,4,2,10,1,2},{5,0,4,2,11,1,3},{5,0,4,2,12,2,3},{5,0,4,2,13,3,3},{5,0,4,2,14,0,3}
};

__constant__ float2 PT[4][4] = {
  {{1.f,0.f},{0.f,0.f},{0.f,0.f},{1.f,0.f}},
  {{0.f,0.f},{1.f,0.f},{1.f,0.f},{0.f,0.f}},
  {{0.f,0.f},{0.f,-1.f},{0.f,1.f},{0.f,0.f}},
  {{1.f,0.f},{0.f,0.f},{0.f,0.f},{-1.f,0.f}}
};

// ---------------- device scratch ----------------
__device__ float2 d_U[256*256];    // U[k*256 + col]
__device__ float  d_M[256*256];    // A = Re(U^dag Z0 U)
__device__ float4 d_mpad[2187];    // 6561 Pauli coeffs, groups of 3 padded to float4
__device__ float2 d_trig[B_*8];    // (sin,cos) of tanh(x@W^T+b)
__device__ float  d_part[9*B_];    // partial contractions per slice

__device__ __forceinline__ float2 cm(float2 a, float2 b){
    return make_float2(a.x*b.x - a.y*b.y, a.x*b.y + a.y*b.x);
}
__device__ __forceinline__ float2 ca(float2 a, float2 b){
    return make_float2(a.x+b.x, a.y+b.y);
}
__device__ __forceinline__ void ffma2(unsigned long long &acc, unsigned long long a, unsigned long long b){
    asm("fma.rn.f32x2 %0, %1, %2, %0;" : "+l"(acc) : "l"(a), "l"(b));
}
__device__ __forceinline__ uint32_t smem_u32(const void* p){
    uint32_t a;
    asm("{ .reg .u64 t; cvta.to.shared.u64 t, %1; cvt.u32.u64 %0, t; }" : "=r"(a) : "l"(p));
    return a;
}
__device__ __forceinline__ void cpasync16(uint32_t saddr, const void* gaddr){
    asm volatile("cp.async.ca.shared.global [%0], [%1], 16;" :: "r"(saddr), "l"(gaddr));
}
__device__ __forceinline__ void cpcommit(){ asm volatile("cp.async.commit_group;" ::: "memory"); }
__device__ __forceinline__ void cpwait2(){ asm volatile("cp.async.wait_group 2;" ::: "memory"); }
__device__ __forceinline__ void cpwait3(){ asm volatile("cp.async.wait_group 3;" ::: "memory"); }
__device__ __forceinline__ void cpwait0(){ asm volatile("cp.async.wait_group 0;" ::: "memory"); }

// ---------------- gate construction (device fn) ----------------
__device__ void make_gate(int g, const float* conv, const float* pool,
                          const float* last, float2* out) {
    GateDesc d = g_desc[g];
    const float* src = (d.src==0) ? conv : ((d.src==1) ? pool : last);
    float2 M[16];
    #pragma unroll
    for (int i=0;i<16;i++) M[i]=make_float2(0.f,0.f);

    if (d.type==0 || d.type==4) {
        float th=src[d.off], ph=src[d.off+1], lam=src[d.off+2];
        float s,c;   sincosf(0.5f*th,&s,&c);
        float sl,cl; sincosf(lam,&sl,&cl);
        float sp,cp; sincosf(ph,&sp,&cp);
        float spl,cpl; sincosf(ph+lam,&spl,&cpl);
        float2 u00=make_float2(c,0.f),       u01=make_float2(-cl*s,-sl*s);
        float2 u10=make_float2(cp*s,sp*s),   u11=make_float2(cpl*c,spl*c);
        if (d.type==0) { M[0]=u00; M[1]=u01; M[2]=u10; M[3]=u11; }
        else {
            M[0]=make_float2(1.f,0.f); M[5]=make_float2(1.f,0.f);
            M[10]=u00; M[11]=u01; M[14]=u10; M[15]=u11;
        }
    } else if (d.type<=3) {
        float phi=src[d.off]; float s,c; sincosf(0.5f*phi,&s,&c);
        if (d.type==1) {
            M[0]=make_float2(c,-s); M[5]=make_float2(c,s);
            M[10]=make_float2(c,s); M[15]=make_float2(c,-s);
        } else {
            M[0]=M[5]=M[10]=M[15]=make_float2(c,0.f);
            if (d.type==3) {
                M[3]=M[6]=M[9]=M[12]=make_float2(0.f,-s);
            } else {
                M[3]=make_float2(0.f,s);  M[6]=make_float2(0.f,-s);
                M[9]=make_float2(0.f,-s); M[12]=make_float2(0.f,s);
            }
        }
    } else {
        float th=src[d.off]; float s,c; sincosf(0.5f*th,&s,&c);
        #pragma unroll
        for (int i=0;i<4;i++)
          #pragma unroll
          for (int j=0;j<4;j++){
            float2 pa = PT[d.w0][(i>>1)*2+(j>>1)];
            float2 pb = PT[d.w1][(i&1)*2+(j&1)];
            float2 K  = cm(pa,pb);
            float2 v  = make_float2(s*K.y, -s*K.x);
            if (i==j) v.x += c;
            M[i*4+j]=v;
        }
    }
    #pragma unroll
    for (int i=0;i<16;i++) out[i]=M[i];
}

// ---------------- 1. build gates (in smem) + evolve 256 basis cols -> U ----------------
__global__ void __launch_bounds__(256) k_build(const float* __restrict__ conv,
                                               const float* __restrict__ pool,
                                               const float* __restrict__ last) {
    __shared__ float2 sG[66*16];
    __shared__ float2 sp[4][256];
    int tid=threadIdx.x, sub=tid>>6, t=tid&63;
    if (tid < 66) make_gate(tid, conv, pool, last, &sG[tid*16]);
    int col = blockIdx.x*4 + sub;
    float2* p = sp[sub];
    for (int k=t;k<256;k+=64) p[k]=make_float2(k==col?1.f:0.f, 0.f);
    __syncthreads();

    for (int g=0; g<66; g++) {
        GateDesc d = g_desc[g];
        const float2* G = sG + g*16;
        if (d.type==0) {
            float2 g0=G[0],g1=G[1],g2=G[2],g3=G[3];
            int pos=7-d.a, mask=1<<pos;
            #pragma unroll
            for (int q=t;q<128;q+=64) {
                int k0 = ((q>>pos)<<(pos+1)) | (q & (mask-1));
                float2 a0=p[k0], a1=p[k0|mask];
                p[k0]      = ca(cm(g0,a0), cm(g1,a1));
                p[k0|mask] = ca(cm(g2,a0), cm(g3,a1));
            }
        } else {
            int pa=7-d.a, pb=7-d.b;
            int p1 = pa<pb?pa:pb, p2 = pa<pb?pb:pa;
            int ma=1<<pa, mb=1<<pb;
            int low = t & ((1<<p1)-1);
            int mid = ((t >> p1) & ((1<<(p2-1-p1))-1)) << (p1+1);
            int hi  = (t >> (p2-1)) << (p2+1);
            int k0 = hi|mid|low;
            float2 v0=p[k0], v1=p[k0|mb], v2=p[k0|ma], v3=p[k0|ma|mb];
            float2 r0 = ca(ca(cm(G[0],v0), cm(G[1],v1)), ca(cm(G[2],v2), cm(G[3],v3)));
            float2 r1 = ca(ca(cm(G[4],v0), cm(G[5],v1)), ca(cm(G[6],v2), cm(G[7],v3)));
            float2 r2 = ca(ca(cm(G[8],v0), cm(G[9],v1)), ca(cm(G[10],v2),cm(G[11],v3)));
            float2 r3 = ca(ca(cm(G[12],v0),cm(G[13],v1)), ca(cm(G[14],v2),cm(G[15],v3)));
            p[k0]=r0; p[k0|mb]=r1; p[k0|ma]=r2; p[k0|ma|mb]=r3;
        }
        __syncthreads();
    }
    for (int k=t;k<256;k+=64) d_U[k*256+col]=p[k];
}

// ---------------- 2. A = Re(U^dag S U), S = Z on bit7 (R8 proven) ----------------
// 256 blocks (row i) x 1024 threads (j, k-quarter); smem reduce
__global__ void __launch_bounds__(1024) k_M() {
    __shared__ float2 su[256];
    __shared__ float  sred[1024];
    int i = blockIdx.x;
    int t = threadIdx.x;
    int j = t & 255, ks = t >> 8;
    if (t < 256) {
        float2 u = d_U[t*256 + i];
        float sgn = (t & 128) ? -1.f : 1.f;
        su[t] = make_float2(u.x*sgn, u.y*sgn);
    }
    __syncthreads();
    unsigned long long acc = 0ull;
    const unsigned long long* ub = (const unsigned long long*)d_U;
    int k0 = ks*64;
    #pragma unroll 8
    for (int k=k0; k<k0+64; k++){
        unsigned long long a = *(const unsigned long long*)&su[k];
        ffma2(acc, a, ub[k*256 + j]);
    }
    float2 v2 = *(float2*)&acc;
    sred[t] = v2.x + v2.y;
    __syncthreads();
    if (ks == 0)
        d_M[i*256 + j] = sred[j] + sred[256+j] + sred[512+j] + sred[768+j];
}

// ---------------- 3. Pauli coefficients via Walsh-Hadamard ----------------
// block = xm (256 blocks), thread = i; H[z] = sum_i (-1)^{popc(i&z)} M[i, i^x]
__global__ void __launch_bounds__(256) k_coeff() {
    __shared__ float sv[256];
    int x = blockIdx.x, tid = threadIdx.x;
    float v = d_M[tid*256 + (tid ^ x)];
    #pragma unroll
    for (int s=0;s<5;s++){
        float p = __shfl_xor_sync(0xffffffffu, v, 1<<s);
        v = (tid & (1<<s)) ? (p - v) : (v + p);
    }
    sv[tid] = v;
    __syncthreads();
    #pragma unroll
    for (int s=5;s<8;s++){
        float p = sv[tid ^ (1<<s)];
        float nv = (tid & (1<<s)) ? (p - v) : (v + p);
        __syncthreads();
        sv[tid] = nv; v = nv;
        __syncthreads();
    }
    int z = tid;
    if ((z & x) == 0) {
        int word = 0, p3 = 1;
        #pragma unroll
        for (int w=0; w<8; w++){
            int dg = ((x>>w)&1) ? 1 : (((z>>w)&1) ? 2 : 0);
            word += dg * p3; p3 *= 3;
        }
        ((float*)d_mpad)[(word/3)*4 + word%3] = v * (1.f/256.f);
    }
}

// ---------------- 4. GEMM + tanh + sincos — barrier-free, self-owned cp.async ----------------
// 256 CTAs x 512 threads, 1 CTA/SM. Mapping IDENTICAL to the proven R6/R8 kernel:
// warps = k-quads (broadcast W reads), lanes = rows, x XOR-swizzled.
// NEW: each thread cp.asyncs exactly the two 16B x-pieces IT will read
// -> own wait_group orders producer->consumer; ZERO __syncthreads in the loop.
// 6 stages give ~3 iterations (>2000 cyc) of WAR margin on slot reuse.
#define NSTG 6
#define GEMM_SMEM (98304 + NSTG*16384)   // 96KB W + 96KB x = 196608 B
__global__ void __launch_bounds__(512,1) k_gemm(const float* __restrict__ x,
                                                const float* __restrict__ w,
                                                const float* __restrict__ b) {
    extern __shared__ float sdyn[];
    float* sW = sdyn;              // [8][3072] = 96KB
    float* sx = sdyn + 8*KDIM;     // [6][64][64] swizzled, 96KB
    int tid = threadIdx.x;
    int warp = tid>>5, lane = tid&31;
    int row0 = blockIdx.x*64;
    uint32_t sW_u = smem_u32(sW);
    uint32_t sx_u = smem_u32(sx);

    // W: 96KB = 6144 x 16B ops, 12 per thread -> group 0 (cooperative, barrier below)
    #pragma unroll
    for (int u=0; u<12; u++){
        int op = tid + u*512;
        cpasync16(sW_u + op*16, (const char*)w + op*16);
    }
    cpcommit();
    // prime stages 0..2: thread loads ITS OWN two pieces (r=lane,lane+32; q=warp)
    #pragma unroll
    for (int s=0; s<3; s++){
        #pragma unroll
        for (int u2=0; u2<2; u2++){
            int r = lane + u2*32;
            int unit = warp ^ (r & 15);
            cpasync16(sx_u + (s*4096 + r*64 + unit*4)*4,
                      x + (size_t)(row0+r)*KDIM + s*64 + warp*4);
        }
        cpcommit();
    }

    // W visibility: W group (oldest of 4) done, one prologue barrier only.
    cpwait3();
    __syncthreads();

    unsigned long long acc[2][8];
    #pragma unroll
    for (int r=0;r<2;r++)
      #pragma unroll
      for (int j=0;j<8;j++) acc[r][j]=0ull;

    for (int c=0; c<48; c++){
        cpwait2();                         // own copies for chunk c complete
        if (c+3 < 48){
            int s = (c+3)%NSTG;
            #pragma unroll
            for (int u2=0; u2<2; u2++){
                int r = lane + u2*32;
                int unit = warp ^ (r & 15);
                cpasync16(sx_u + (s*4096 + r*64 + unit*4)*4,
                          x + (size_t)(row0+r)*KDIM + (c+3)*64 + warp*4);
            }
        }
        cpcommit();
        int s = c%NSTG;
        // W slice for this warp's k-quad: broadcast loads (uniform address)
        unsigned long long wlo[8], whi[8];
        #pragma unroll
        for (int j=0;j<8;j++){
            float4 wf = *(const float4*)&sW[j*KDIM + c*64 + warp*4];
            wlo[j] = *(unsigned long long*)&wf.x;
            whi[j] = *(unsigned long long*)&wf.z;
        }
        #pragma unroll
        for (int r2=0;r2<2;r2++){
            int r = lane + r2*32;
            int unit = warp ^ (r & 15);
            float4 xf = *(const float4*)&sx[s*4096 + r*64 + unit*4];
            unsigned long long xl = *(unsigned long long*)&xf.x;
            unsigned long long xh = *(unsigned long long*)&xf.z;
            #pragma unroll
            for (int j=0;j<8;j++){
                ffma2(acc[r2][j], xl, wlo[j]);
                ffma2(acc[r2][j], xh, whi[j]);
            }
        }
    }

    // drain own copies, then cross-warp k-reduction via smem (reuse sx: 32KB)
    cpwait0();
    __syncthreads();
    float* sred = sx;
    #pragma unroll
    for (int r2=0;r2<2;r2++){
        int r = lane + r2*32;
        #pragma unroll
        for (int j=0;j<8;j++){
            float2 v = *(float2*)&acc[r2][j];
            sred[(warp*64 + r)*8 + j] = v.x + v.y;
        }
    }
    __syncthreads();
    {
        int r = tid>>3, j = tid&7;   // 512 threads = 64 rows x 8 outputs
        float a = 0.f;
        #pragma unroll
        for (int wp=0; wp<16; wp++) a += sred[(wp*64 + r)*8 + j];
        float th = tanhf(a + b[j]);
        float sn, cs; sincosf(th,&sn,&cs);
        d_trig[(row0+r)*8 + j] = make_float2(sn,cs);
    }
}

// ---------------- 5. contraction, 9 slices (p0,p1) — R8 proven ----------------
__global__ void __launch_bounds__(256) k_contract() {
    __shared__ float4 sm[243];
    int tid = threadIdx.x;
    int s01 = blockIdx.y;
    if (tid < 243) sm[tid] = d_mpad[s01*243 + tid];
    __syncthreads();

    int bidx = blockIdx.x*256 + tid;
    float2 tg[8];
    #pragma unroll
    for (int w=0;w<8;w++) tg[w] = d_trig[bidx*8 + w];

    float g2[3]={1.f,tg[2].x,tg[2].y}, g3[3]={1.f,tg[3].x,tg[3].y};
    float g4[3]={1.f,tg[4].x,tg[4].y}, g5[3]={1.f,tg[5].x,tg[5].y};
    float g6[3]={1.f,tg[6].x,tg[6].y};
    float s7=tg[7].x, c7=tg[7].y;

    float z=0.f; int idx=0;
    #pragma unroll 1
    for (int i2=0;i2<3;i2++){ float p2=g2[i2];
      #pragma unroll 1
      for (int i3=0;i3<3;i3++){ float p3=p2*g3[i3];
        #pragma unroll 1
        for (int i4=0;i4<3;i4++){ float p4=p3*g4[i4];
          #pragma unroll
          for (int i5=0;i5<3;i5++){ float p5=p4*g5[i5];
            #pragma unroll
            for (int i6=0;i6<3;i6++){ float p6=p5*g6[i6];
              float4 m = sm[idx++];
              z += p6*(m.x + m.y*s7 + m.z*c7);
            }
          }
        }
      }
    }
    int s0=s01/3, s1=s01%3;
    float f0 = (s0==0)?1.f:((s0==1)?tg[0].x:tg[0].y);
    float f1 = (s1==0)?1.f:((s1==1)?tg[1].x:tg[1].y);
    d_part[s01*B_ + bidx] = z * f0 * f1;
}

// ---------------- 6. logits ----------------
__global__ void __launch_bounds__(256) k_logits(const float* __restrict__ ow,
                                                const float* __restrict__ ob,
                                                float* __restrict__ out) {
    int bidx = blockIdx.x*256 + threadIdx.x;
    float z = 0.f;
    #pragma unroll
    for (int s=0;s<9;s++) z += d_part[s*B_ + bidx];
    #pragma unroll
    for (int c=0;c<10;c++) out[bidx*10 + c] = z*ow[c] + ob[c];
}

// ---------------- launch (R8 submission order, byte-identical) ----------------
extern "C" void kernel_launch(void* const* d_in, const int* in_sizes, int n_in,
                              void* d_out, int out_size) {
    const float* x    = (const float*)d_in[0];
    const float* fw   = (const float*)d_in[1];
    const float* fb   = (const float*)d_in[2];
    const float* conv = (const float*)d_in[3];
    const float* pool = (const float*)d_in[4];
    const float* last = (const float*)d_in[5];
    const float* ow   = (const float*)d_in[6];
    const float* ob   = (const float*)d_in[7];
    float* out = (float*)d_out;

    static int inited = 0;
    static cudaStream_t s2;
    static cudaEvent_t evFork, evJoin;
    if (!inited) {
        cudaFuncSetAttribute(k_gemm, cudaFuncAttributeMaxDynamicSharedMemorySize, GEMM_SMEM);
        cudaStreamCreateWithFlags(&s2, cudaStreamNonBlocking);
        cudaEventCreateWithFlags(&evFork, cudaEventDisableTiming);
        cudaEventCreateWithFlags(&evJoin, cudaEventDisableTiming);
        inited = 1;
    }

    // fork: circuit chain (build -> M -> coeff) on s2, gemm on main stream
    cudaEventRecord(evFork, 0);
    cudaStreamWaitEvent(s2, evFork, 0);

    k_build<<<64,256,0,s2>>>(conv, pool, last);
    k_M<<<256,1024,0,s2>>>();
    k_coeff<<<256,256,0,s2>>>();
    cudaEventRecord(evJoin, s2);

    k_gemm<<<256,512,GEMM_SMEM>>>(x, fw, fb);

    // join: contract needs both branches
    cudaStreamWaitEvent(0, evJoin, 0);
    dim3 gc(64,9);
    k_contract<<<gc,256>>>();
    k_logits<<<64,256>>>(ow, ob, out);
}

// round 16
// speedup vs baseline: 2.6366x; 1.4185x over previous
#include <cuda_runtime.h>
#include <math.h>
#include <stdint.h>

#define B_   16384
#define KDIM 3072

// ---------------- gate descriptor table ----------------
// type: 0=U3(wire a), 1=ZZ(a,b), 2=YY, 3=XX, 4=CU3(ctrl=a,tgt=b), 5=ARB(pauli w0 on a, w1 on b)
typedef struct { int type, a, b, src, off, w0, w1; } GateDesc;

__constant__ GateDesc g_desc[66] = {
  {0,0,0,0,0,0,0},{0,2,0,0,33,0,0},{1,0,2,0,6,0,0},{2,0,2,0,7,0,0},{3,0,2,0,8,0,0},{0,0,0,0,9,0,0},{0,2,0,0,42,0,0},
  {0,1,0,0,15,0,0},{0,3,0,0,48,0,0},{1,1,3,0,21,0,0},{2,1,3,0,22,0,0},{3,1,3,0,23,0,0},{0,1,0,0,24,0,0},{0,3,0,0,57,0,0},
  {0,4,0,0,60,0,0},{0,6,0,0,93,0,0},{1,4,6,0,66,0,0},{2,4,6,0,67,0,0},{3,4,6,0,68,0,0},{0,4,0,0,69,0,0},{0,6,0,0,102,0,0},
  {0,5,0,0,75,0,0},{0,7,0,0,108,0,0},{1,5,7,0,81,0,0},{2,5,7,0,82,0,0},{3,5,7,0,83,0,0},{0,5,0,0,84,0,0},{0,7,0,0,117,0,0},
  {4,1,0,1,0,0,0},{4,3,2,1,3,0,0},{4,5,4,1,6,0,0},{4,7,6,1,9,0,0},
  {0,0,0,0,120,0,0},{0,2,0,0,153,0,0},{1,0,2,0,126,0,0},{2,0,2,0,127,0,0},{3,0,2,0,128,0,0},{0,0,0,0,129,0,0},{0,2,0,0,162,0,0},
  {0,4,0,0,180,0,0},{0,4,0,0,183,0,0},{0,4,0,0,186,0,0},{0,4,0,0,189,0,0},{0,4,0,0,192,0,0},
  {0,6,0,0,210,0,0},{0,6,0,0,213,0,0},{0,6,0,0,216,0,0},{0,6,0,0,219,0,0},{0,6,0,0,222,0,0},
  {4,2,0,1,12,0,0},{4,6,4,1,15,0,0},
  {5,0,4,2,0,1,0},{5,0,4,2,1,2,0},{5,0,4,2,2,3,0},{5,0,4,2,3,3,1},{5,0,4,2,4,0,1},
  {5,0,4,2,5,1,1},{5,0,4,2,6,2,1},{5,0,4,2,7,2,2},{5,0,4,2,8,3,2},{5,0,4,2,9,0,2},
  {5,0,4,2,10,1,2},{5,0,4,2,11,1,3},{5,0,4,2,12,2,3},{5,0,4,2,13,3,3},{5,0,4,2,14,0,3}
};

__constant__ float2 PT[4][4] = {
  {{1.f,0.f},{0.f,0.f},{0.f,0.f},{1.f,0.f}},
  {{0.f,0.f},{1.f,0.f},{1.f,0.f},{0.f,0.f}},
  {{0.f,0.f},{0.f,-1.f},{0.f,1.f},{0.f,0.f}},
  {{1.f,0.f},{0.f,0.f},{0.f,0.f},{-1.f,0.f}}
};

// ---------------- device scratch ----------------
__device__ float2 d_U[256*256];    // U[k*256 + col]
__device__ float  d_M[256*256];    // A = Re(U^dag Z0 U)
__device__ float4 d_mpad[2187];    // 6561 Pauli coeffs, groups of 3 padded to float4
__device__ float2 d_trig[B_*8];    // (sin,cos) of tanh(x@W^T+b)
__device__ float  d_part[9*B_];    // partial contractions per slice

__device__ __forceinline__ float2 cm(float2 a, float2 b){
    return make_float2(a.x*b.x - a.y*b.y, a.x*b.y + a.y*b.x);
}
__device__ __forceinline__ float2 ca(float2 a, float2 b){
    return make_float2(a.x+b.x, a.y+b.y);
}
__device__ __forceinline__ void ffma2(unsigned long long &acc, unsigned long long a, unsigned long long b){
    asm("fma.rn.f32x2 %0, %1, %2, %0;" : "+l"(acc) : "l"(a), "l"(b));
}
__device__ __forceinline__ uint32_t smem_u32(const void* p){
    uint32_t a;
    asm("{ .reg .u64 t; cvta.to.shared.u64 t, %1; cvt.u32.u64 %0, t; }" : "=r"(a) : "l"(p));
    return a;
}
__device__ __forceinline__ void cpasync16(uint32_t saddr, const void* gaddr){
    asm volatile("cp.async.ca.shared.global [%0], [%1], 16;" :: "r"(saddr), "l"(gaddr));
}
__device__ __forceinline__ void cpcommit(){ asm volatile("cp.async.commit_group;" ::: "memory"); }
__device__ __forceinline__ void cpwait2(){ asm volatile("cp.async.wait_group 2;" ::: "memory"); }
__device__ __forceinline__ void cpwait4(){ asm volatile("cp.async.wait_group 4;" ::: "memory"); }

// ---------------- gate construction (device fn) ----------------
__device__ void make_gate(int g, const float* conv, const float* pool,
                          const float* last, float2* out) {
    GateDesc d = g_desc[g];
    const float* src = (d.src==0) ? conv : ((d.src==1) ? pool : last);
    float2 M[16];
    #pragma unroll
    for (int i=0;i<16;i++) M[i]=make_float2(0.f,0.f);

    if (d.type==0 || d.type==4) {
        float th=src[d.off], ph=src[d.off+1], lam=src[d.off+2];
        float s,c;   sincosf(0.5f*th,&s,&c);
        float sl,cl; sincosf(lam,&sl,&cl);
        float sp,cp; sincosf(ph,&sp,&cp);
        float spl,cpl; sincosf(ph+lam,&spl,&cpl);
        float2 u00=make_float2(c,0.f),       u01=make_float2(-cl*s,-sl*s);
        float2 u10=make_float2(cp*s,sp*s),   u11=make_float2(cpl*c,spl*c);
        if (d.type==0) { M[0]=u00; M[1]=u01; M[2]=u10; M[3]=u11; }
        else {
            M[0]=make_float2(1.f,0.f); M[5]=make_float2(1.f,0.f);
            M[10]=u00; M[11]=u01; M[14]=u10; M[15]=u11;
        }
    } else if (d.type<=3) {
        float phi=src[d.off]; float s,c; sincosf(0.5f*phi,&s,&c);
        if (d.type==1) {
            M[0]=make_float2(c,-s); M[5]=make_float2(c,s);
            M[10]=make_float2(c,s); M[15]=make_float2(c,-s);
        } else {
            M[0]=M[5]=M[10]=M[15]=make_float2(c,0.f);
            if (d.type==3) {
                M[3]=M[6]=M[9]=M[12]=make_float2(0.f,-s);
            } else {
                M[3]=make_float2(0.f,s);  M[6]=make_float2(0.f,-s);
                M[9]=make_float2(0.f,-s); M[12]=make_float2(0.f,s);
            }
        }
    } else {
        float th=src[d.off]; float s,c; sincosf(0.5f*th,&s,&c);
        #pragma unroll
        for (int i=0;i<4;i++)
          #pragma unroll
          for (int j=0;j<4;j++){
            float2 pa = PT[d.w0][(i>>1)*2+(j>>1)];
            float2 pb = PT[d.w1][(i&1)*2+(j&1)];
            float2 K  = cm(pa,pb);
            float2 v  = make_float2(s*K.y, -s*K.x);
            if (i==j) v.x += c;
            M[i*4+j]=v;
        }
    }
    #pragma unroll
    for (int i=0;i<16;i++) out[i]=M[i];
}

// ---------------- 1. build gates (in smem) + evolve 256 basis cols -> U ----------------
__global__ void __launch_bounds__(256) k_build(const float* __restrict__ conv,
                                               const float* __restrict__ pool,
                                               const float* __restrict__ last) {
    __shared__ float2 sG[66*16];
    __shared__ float2 sp[4][256];
    int tid=threadIdx.x, sub=tid>>6, t=tid&63;
    if (tid < 66) make_gate(tid, conv, pool, last, &sG[tid*16]);
    int col = blockIdx.x*4 + sub;
    float2* p = sp[sub];
    for (int k=t;k<256;k+=64) p[k]=make_float2(k==col?1.f:0.f, 0.f);
    __syncthreads();

    for (int g=0; g<66; g++) {
        GateDesc d = g_desc[g];
        const float2* G = sG + g*16;
        if (d.type==0) {
            float2 g0=G[0],g1=G[1],g2=G[2],g3=G[3];
            int pos=7-d.a, mask=1<<pos;
            #pragma unroll
            for (int q=t;q<128;q+=64) {
                int k0 = ((q>>pos)<<(pos+1)) | (q & (mask-1));
                float2 a0=p[k0], a1=p[k0|mask];
                p[k0]      = ca(cm(g0,a0), cm(g1,a1));
                p[k0|mask] = ca(cm(g2,a0), cm(g3,a1));
            }
        } else {
            int pa=7-d.a, pb=7-d.b;
            int p1 = pa<pb?pa:pb, p2 = pa<pb?pb:pa;
            int ma=1<<pa, mb=1<<pb;
            int low = t & ((1<<p1)-1);
            int mid = ((t >> p1) & ((1<<(p2-1-p1))-1)) << (p1+1);
            int hi  = (t >> (p2-1)) << (p2+1);
            int k0 = hi|mid|low;
            float2 v0=p[k0], v1=p[k0|mb], v2=p[k0|ma], v3=p[k0|ma|mb];
            float2 r0 = ca(ca(cm(G[0],v0), cm(G[1],v1)), ca(cm(G[2],v2), cm(G[3],v3)));
            float2 r1 = ca(ca(cm(G[4],v0), cm(G[5],v1)), ca(cm(G[6],v2), cm(G[7],v3)));
            float2 r2 = ca(ca(cm(G[8],v0), cm(G[9],v1)), ca(cm(G[10],v2),cm(G[11],v3)));
            float2 r3 = ca(ca(cm(G[12],v0),cm(G[13],v1)), ca(cm(G[14],v2),cm(G[15],v3)));
            p[k0]=r0; p[k0|mb]=r1; p[k0|ma]=r2; p[k0|ma|mb]=r3;
        }
        __syncthreads();
    }
    for (int k=t;k<256;k+=64) d_U[k*256+col]=p[k];
}

// ---------------- 2. A = Re(U^dag S U), S = Z on bit7 (R8 proven) ----------------
// 256 blocks (row i) x 1024 threads (j, k-quarter); smem reduce
__global__ void __launch_bounds__(1024) k_M() {
    __shared__ float2 su[256];
    __shared__ float  sred[1024];
    int i = blockIdx.x;
    int t = threadIdx.x;
    int j = t & 255, ks = t >> 8;
    if (t < 256) {
        float2 u = d_U[t*256 + i];
        float sgn = (t & 128) ? -1.f : 1.f;
        su[t] = make_float2(u.x*sgn, u.y*sgn);
    }
    __syncthreads();
    unsigned long long acc = 0ull;
    const unsigned long long* ub = (const unsigned long long*)d_U;
    int k0 = ks*64;
    #pragma unroll 8
    for (int k=k0; k<k0+64; k++){
        unsigned long long a = *(const unsigned long long*)&su[k];
        ffma2(acc, a, ub[k*256 + j]);
    }
    float2 v2 = *(float2*)&acc;
    sred[t] = v2.x + v2.y;
    __syncthreads();
    if (ks == 0)
        d_M[i*256 + j] = sred[j] + sred[256+j] + sred[512+j] + sred[768+j];
}

// ---------------- 3. Pauli coefficients via Walsh-Hadamard ----------------
// block = xm (256 blocks), thread = i; H[z] = sum_i (-1)^{popc(i&z)} M[i, i^x]
__global__ void __launch_bounds__(256) k_coeff() {
    __shared__ float sv[256];
    int x = blockIdx.x, tid = threadIdx.x;
    float v = d_M[tid*256 + (tid ^ x)];
    #pragma unroll
    for (int s=0;s<5;s++){
        float p = __shfl_xor_sync(0xffffffffu, v, 1<<s);
        v = (tid & (1<<s)) ? (p - v) : (v + p);
    }
    sv[tid] = v;
    __syncthreads();
    #pragma unroll
    for (int s=5;s<8;s++){
        float p = sv[tid ^ (1<<s)];
        float nv = (tid & (1<<s)) ? (p - v) : (v + p);
        __syncthreads();
        sv[tid] = nv; v = nv;
        __syncthreads();
    }
    int z = tid;
    if ((z & x) == 0) {
        int word = 0, p3 = 1;
        #pragma unroll
        for (int w=0; w<8; w++){
            int dg = ((x>>w)&1) ? 1 : (((z>>w)&1) ? 2 : 0);
            word += dg * p3; p3 *= 3;
        }
        ((float*)d_mpad)[(word/3)*4 + word%3] = v * (1.f/256.f);
    }
}

// ---------------- 4. GEMM + tanh + sincos — R6 body, barriers halved ----------------
// 256 CTAs x 512 threads, 1 CTA/SM. Warps = k-quads (broadcast W reads),
// lanes = rows, x XOR-swizzled — fill/compute byte-identical to the proven R6.
// NEW: 6 stages, prefetch distance 4, sync only on EVEN chunks:
//   even c: wait_group 2 (completes chunks c AND c+1 for every thread)
//           + one __syncthreads (publishes all copies + orders slot WAR).
//   odd  c: no wait, no barrier — its data was proven complete & visible
//           at the preceding even barrier. 24 barriers instead of 48.
#define NSTG 6
#define GEMM_SMEM (98304 + NSTG*16384)   // 96KB W + 96KB x = 196608 B
__global__ void __launch_bounds__(512,1) k_gemm(const float* __restrict__ x,
                                                const float* __restrict__ w,
                                                const float* __restrict__ b) {
    extern __shared__ float sdyn[];
    float* sW = sdyn;              // [8][3072] = 96KB
    float* sx = sdyn + 8*KDIM;     // [6][64][64] swizzled, 96KB
    int tid = threadIdx.x;
    int warp = tid>>5, lane = tid&31;
    int row0 = blockIdx.x*64;
    uint32_t sW_u = smem_u32(sW);
    uint32_t sx_u = smem_u32(sx);

    // W: 96KB = 6144 x 16B ops, 12 per thread -> group 0 (oldest)
    #pragma unroll
    for (int u=0; u<12; u++){
        int op = tid + u*512;
        cpasync16(sW_u + op*16, (const char*)w + op*16);
    }
    cpcommit();
    // prime stages 0..3 (x tile: row r, k-quad q stored at unit q^(r&15))
    #pragma unroll
    for (int s=0; s<4; s++){
        #pragma unroll
        for (int u=0; u<2; u++){
            int op = tid + u*512;          // 0..1023
            int r = op>>4, q = op&15;
            int unit = q ^ (r & 15);
            cpasync16(sx_u + (s*4096 + r*64 + unit*4)*4,
                      x + (size_t)(row0+r)*KDIM + s*64 + q*4);
        }
        cpcommit();
    }

    // W visibility (W group is the oldest of 5 pending)
    cpwait4();
    __syncthreads();

    unsigned long long acc[2][8];
    #pragma unroll
    for (int r=0;r<2;r++)
      #pragma unroll
      for (int j=0;j<8;j++) acc[r][j]=0ull;

    int slot_c = 0;   // slot of chunk c
    int slot_p = 4;   // slot of chunk c+4
    for (int c=0; c<48; c++){
        if ((c & 1) == 0){
            cpwait2();            // chunks c, c+1 complete (every thread)
            __syncthreads();      // publish all copies; order WAR on slots
        }
        // prefetch chunk c+4 (uniform empty commit at tail keeps counts exact)
        if (c+4 < 48){
            #pragma unroll
            for (int u=0; u<2; u++){
                int op = tid + u*512;
                int r = op>>4, q = op&15;
                int unit = q ^ (r & 15);
                cpasync16(sx_u + (slot_p*4096 + r*64 + unit*4)*4,
                          x + (size_t)(row0+r)*KDIM + (c+4)*64 + q*4);
            }
        }
        cpcommit();
        // W slice for this warp's k-quad: broadcast loads (uniform address)
        unsigned long long wlo[8], whi[8];
        #pragma unroll
        for (int j=0;j<8;j++){
            float4 wf = *(const float4*)&sW[j*KDIM + c*64 + warp*4];
            wlo[j] = *(unsigned long long*)&wf.x;
            whi[j] = *(unsigned long long*)&wf.z;
        }
        #pragma unroll
        for (int r2=0;r2<2;r2++){
            int r = lane + r2*32;
            int unit = warp ^ (r & 15);
            float4 xf = *(const float4*)&sx[slot_c*4096 + r*64 + unit*4];
            unsigned long long xl = *(unsigned long long*)&xf.x;
            unsigned long long xh = *(unsigned long long*)&xf.z;
            #pragma unroll
            for (int j=0;j<8;j++){
                ffma2(acc[r2][j], xl, wlo[j]);
                ffma2(acc[r2][j], xh, whi[j]);
            }
        }
        slot_c = (slot_c==NSTG-1) ? 0 : slot_c+1;
        slot_p = (slot_p==NSTG-1) ? 0 : slot_p+1;
    }

    // cross-warp k-reduction via smem (reuse sx: 16*64*8 floats = 32KB)
    __syncthreads();
    float* sred = sx;
    #pragma unroll
    for (int r2=0;r2<2;r2++){
        int r = lane + r2*32;
        #pragma unroll
        for (int j=0;j<8;j++){
            float2 v = *(float2*)&acc[r2][j];
            sred[(warp*64 + r)*8 + j] = v.x + v.y;
        }
    }
    __syncthreads();
    {
        int r = tid>>3, j = tid&7;   // 512 threads = 64 rows x 8 outputs
        float a = 0.f;
        #pragma unroll
        for (int wp=0; wp<16; wp++) a += sred[(wp*64 + r)*8 + j];
        float th = tanhf(a + b[j]);
        float sn, cs; sincosf(th,&sn,&cs);
        d_trig[(row0+r)*8 + j] = make_float2(sn,cs);
    }
}

// ---------------- 5. contraction, 9 slices (p0,p1) — R8 proven ----------------
__global__ void __launch_bounds__(256) k_contract() {
    __shared__ float4 sm[243];
    int tid = threadIdx.x;
    int s01 = blockIdx.y;
    if (tid < 243) sm[tid] = d_mpad[s01*243 + tid];
    __syncthreads();

    int bidx = blockIdx.x*256 + tid;
    float2 tg[8];
    #pragma unroll
    for (int w=0;w<8;w++) tg[w] = d_trig[bidx*8 + w];

    float g2[3]={1.f,tg[2].x,tg[2].y}, g3[3]={1.f,tg[3].x,tg[3].y};
    float g4[3]={1.f,tg[4].x,tg[4].y}, g5[3]={1.f,tg[5].x,tg[5].y};
    float g6[3]={1.f,tg[6].x,tg[6].y};
    float s7=tg[7].x, c7=tg[7].y;

    float z=0.f; int idx=0;
    #pragma unroll 1
    for (int i2=0;i2<3;i2++){ float p2=g2[i2];
      #pragma unroll 1
      for (int i3=0;i3<3;i3++){ float p3=p2*g3[i3];
        #pragma unroll 1
        for (int i4=0;i4<3;i4++){ float p4=p3*g4[i4];
          #pragma unroll
          for (int i5=0;i5<3;i5++){ float p5=p4*g5[i5];
            #pragma unroll
            for (int i6=0;i6<3;i6++){ float p6=p5*g6[i6];
              float4 m = sm[idx++];
              z += p6*(m.x + m.y*s7 + m.z*c7);
            }
          }
        }
      }
    }
    int s0=s01/3, s1=s01%3;
    float f0 = (s0==0)?1.f:((s0==1)?tg[0].x:tg[0].y);
    float f1 = (s1==0)?1.f:((s1==1)?tg[1].x:tg[1].y);
    d_part[s01*B_ + bidx] = z * f0 * f1;
}

// ---------------- 6. logits ----------------
__global__ void __launch_bounds__(256) k_logits(const float* __restrict__ ow,
                                                const float* __restrict__ ob,
                                                float* __restrict__ out) {
    int bidx = blockIdx.x*256 + threadIdx.x;
    float z = 0.f;
    #pragma unroll
    for (int s=0;s<9;s++) z += d_part[s*B_ + bidx];
    #pragma unroll
    for (int c=0;c<10;c++) out[bidx*10 + c] = z*ow[c] + ob[c];
}

// ---------------- launch (R8 submission order, byte-identical) ----------------
extern "C" void kernel_launch(void* const* d_in, const int* in_sizes, int n_in,
                              void* d_out, int out_size) {
    const float* x    = (const float*)d_in[0];
    const float* fw   = (const float*)d_in[1];
    const float* fb   = (const float*)d_in[2];
    const float* conv = (const float*)d_in[3];
    const float* pool = (const float*)d_in[4];
    const float* last = (const float*)d_in[5];
    const float* ow   = (const float*)d_in[6];
    const float* ob   = (const float*)d_in[7];
    float* out = (float*)d_out;

    static int inited = 0;
    static cudaStream_t s2;
    static cudaEvent_t evFork, evJoin;
    if (!inited) {
        cudaFuncSetAttribute(k_gemm, cudaFuncAttributeMaxDynamicSharedMemorySize, GEMM_SMEM);
        cudaStreamCreateWithFlags(&s2, cudaStreamNonBlocking);
        cudaEventCreateWithFlags(&evFork, cudaEventDisableTiming);
        cudaEventCreateWithFlags(&evJoin, cudaEventDisableTiming);
        inited = 1;
    }

    // fork: circuit chain (build -> M -> coeff) on s2, gemm on main stream
    cudaEventRecord(evFork, 0);
    cudaStreamWaitEvent(s2, evFork, 0);

    k_build<<<64,256,0,s2>>>(conv, pool, last);
    k_M<<<256,1024,0,s2>>>();
    k_coeff<<<256,256,0,s2>>>();
    cudaEventRecord(evJoin, s2);

    k_gemm<<<256,512,GEMM_SMEM>>>(x, fw, fb);

    // join: contract needs both branches
    cudaStreamWaitEvent(0, evJoin, 0);
    dim3 gc(64,9);
    k_contract<<<gc,256>>>();
    k_logits<<<64,256>>>(ow, ob, out);
}